// round 9
// baseline (speedup 1.0000x reference)
#include <cuda_runtime.h>
#include <cstdint>

#define HD   19      // hidden size
#define HJ   20      // padded hidden (bank/pad stride)
#define DD   64      // input size
#define TPB  128
#define NPART 1024

__device__ float g_partials[NPART];

struct Tables {
    float WiT[DD * HJ];   // [k][j] = Wi[j][k]
    float WrT[HD * HJ];   // [k][j] = Wr[j][k]
    float WoT[HD * HJ];   // [k][j] = Wo[j][k]
    float bi[HJ];
    float bo[HJ];
    float bdt[HJ];        // dt / tau_dyn, pad = 0
};
__device__ Tables g_tab;
#define TAB_F ((int)(sizeof(Tables) / 4))

static __device__ __forceinline__ float tanha(float v) {
    float r; asm("tanh.approx.f32 %0,%1;" : "=f"(r) : "f"(v)); return r;
}

// ---------- kernel A: per-block partial sums of |x| ----------
__global__ void __launch_bounds__(256) k_a_red(const float4* __restrict__ x, int n4) {
    float s = 0.f;
    for (int i = blockIdx.x * blockDim.x + threadIdx.x; i < n4;
         i += gridDim.x * blockDim.x) {
        float4 v = x[i];
        s += fabsf(v.x) + fabsf(v.y) + fabsf(v.z) + fabsf(v.w);
    }
#pragma unroll
    for (int o = 16; o > 0; o >>= 1) s += __shfl_down_sync(0xffffffffu, s, o);
    __shared__ float ws[8];
    int w = threadIdx.x >> 5, l = threadIdx.x & 31;
    if (l == 0) ws[w] = s;
    __syncthreads();
    if (threadIdx.x == 0) {
        float t = 0.f;
#pragma unroll
        for (int i = 0; i < 8; i++) t += ws[i];
        g_partials[blockIdx.x] = t;
    }
}

// ---------- kernel B: finish reduction + build transposed tables ----------
__global__ void __launch_bounds__(256) k_prep(
    const float* __restrict__ Wi, const float* __restrict__ bi,
    const float* __restrict__ Wr, const float* __restrict__ Wo,
    const float* __restrict__ bo, const float* __restrict__ tau,
    const float* __restrict__ ta, float invN)
{
    __shared__ float red[256];
    __shared__ float urg_s;
    int t = threadIdx.x;

    float s = 0.f;
    for (int i = t; i < NPART; i += 256) s += g_partials[i];
    red[t] = s;
    __syncthreads();
#pragma unroll
    for (int o = 128; o > 0; o >>= 1) {
        if (t < o) red[t] += red[t + o];
        __syncthreads();
    }
    if (t == 0) urg_s = fmaxf(red[0] * invN, 0.01f);

    float* gt = (float*)&g_tab;
    for (int i = t; i < TAB_F; i += 256) gt[i] = 0.f;
    __syncthreads();
    float urg = urg_s;

    for (int i = t; i < DD * HD; i += 256) {
        int k = i / HD, j = i % HD;
        g_tab.WiT[k * HJ + j] = Wi[j * DD + k];
    }
    for (int i = t; i < HD * HD; i += 256) {
        int k = i / HD, j = i % HD;
        g_tab.WrT[k * HJ + j] = Wr[j * HD + k];
        g_tab.WoT[k * HJ + j] = Wo[j * HD + k];
    }
    if (t < HD) {
        g_tab.bi[t] = bi[t];
        g_tab.bo[t] = bo[t];
        float td = tau[t] * (1.0f - ta[t]) + ta[t] / urg;
        td = fminf(fmaxf(td, 0.01f), 10.0f);
        g_tab.bdt[t] = 0.01f / td;
    }
}

// ---------- kernel C: fused, scalar, 1 row/thread, high occupancy ----------
__global__ void __launch_bounds__(TPB, 5)
k_main(const float* __restrict__ x, const int* __restrict__ steps_p,
       float* __restrict__ out, float* __restrict__ hout)
{
    __shared__ float sWi[DD * HJ];      // 5120 B
    __shared__ float sWr[HD * HJ];      // 1520 B
    __shared__ float sWo[HD * HJ];      // 1520 B
    __shared__ float sBi[HJ], sBo[HJ], sBd[HJ];
    __shared__ float fst[TPB * HD];     // 9728 B staging

    const int tid = threadIdx.x;
    {
        const float* gt = (const float*)&g_tab;
        for (int i = tid; i < DD * HJ; i += TPB) sWi[i] = gt[i];
        const float* g1 = gt + DD * HJ;
        for (int i = tid; i < HD * HJ; i += TPB) sWr[i] = g1[i];
        const float* g2 = g1 + HD * HJ;
        for (int i = tid; i < HD * HJ; i += TPB) sWo[i] = g2[i];
        const float* g3 = g2 + HD * HJ;
        if (tid < HJ) {
            sBi[tid] = g3[tid];
            sBo[tid] = g3[HJ + tid];
            sBd[tid] = g3[2 * HJ + tid];
        }
    }
    __syncthreads();

    const size_t row = (size_t)blockIdx.x * TPB + tid;
    const float4* xr = (const float4*)(x + row * DD);

    // ---- phase 1: mapped = x @ Wi^T + bi ----
    float m[HD];
#pragma unroll
    for (int j = 0; j < HD; j++) m[j] = sBi[j];
#pragma unroll 4
    for (int q = 0; q < DD / 4; q++) {
        float4 v = xr[q];
        float vv[4] = {v.x, v.y, v.z, v.w};
#pragma unroll
        for (int e = 0; e < 4; e++) {
            const float* w = &sWi[(q * 4 + e) * HJ];
            float xk = vv[e];
#pragma unroll
            for (int j = 0; j < HD; j++) m[j] = fmaf(xk, w[j], m[j]);
        }
    }

    // ---- phase 2: recurrence ----
    float h[HD];
#pragma unroll
    for (int j = 0; j < HD; j++) h[j] = 0.f;

    const int steps = *steps_p;
    for (int s = 0; s < steps; s++) {
        float a[HD];
#pragma unroll
        for (int j = 0; j < HD; j++) a[j] = m[j];
#pragma unroll
        for (int k = 0; k < HD; k++) {
            const float* w = &sWr[k * HJ];
            float hk = h[k];
#pragma unroll
            for (int j = 0; j < HD; j++) a[j] = fmaf(hk, w[j], a[j]);
        }
#pragma unroll
        for (int j = 0; j < HD; j++)
            h[j] = fmaf(sBd[j], tanha(a[j]) - h[j], h[j]);
    }

    // ---- phase 3: out = h @ Wo^T + bo (reuse m as accumulator) ----
#pragma unroll
    for (int j = 0; j < HD; j++) m[j] = sBo[j];
#pragma unroll
    for (int k = 0; k < HD; k++) {
        const float* w = &sWo[k * HJ];
        float hk = h[k];
#pragma unroll
        for (int j = 0; j < HD; j++) m[j] = fmaf(hk, w[j], m[j]);
    }

    // ---- stage + coalesced stores ----
#pragma unroll
    for (int j = 0; j < HD; j++) fst[tid * HD + j] = m[j];
    __syncthreads();
    {
        float4* go = (float4*)(out + (size_t)blockIdx.x * (TPB * HD));
        const float4* f4 = (const float4*)fst;
        for (int i = tid; i < TPB * HD / 4; i += TPB) go[i] = f4[i];
    }
    if (hout) {
        __syncthreads();
#pragma unroll
        for (int j = 0; j < HD; j++) fst[tid * HD + j] = h[j];
        __syncthreads();
        float4* gh = (float4*)(hout + (size_t)blockIdx.x * (TPB * HD));
        const float4* f4 = (const float4*)fst;
        for (int i = tid; i < TPB * HD / 4; i += TPB) gh[i] = f4[i];
    }
}

extern "C" void kernel_launch(void* const* d_in, const int* in_sizes, int n_in,
                              void* d_out, int out_size) {
    const float* x   = (const float*)d_in[0];
    const float* Wi  = (const float*)d_in[1];
    const float* bi  = (const float*)d_in[2];
    const float* Wr  = (const float*)d_in[3];
    const float* Wo  = (const float*)d_in[4];
    const float* bo  = (const float*)d_in[5];
    const float* tau = (const float*)d_in[6];
    const float* ta  = (const float*)d_in[7];
    const int* steps = (const int*)d_in[8];

    const int nx = in_sizes[0];
    const int B  = nx / DD;

    float* out = (float*)d_out;
    long long bh = (long long)B * HD;
    float* hout = ((long long)out_size >= 2 * bh) ? (out + bh) : nullptr;

    k_a_red<<<NPART, 256>>>((const float4*)x, nx / 4);
    k_prep<<<1, 256>>>(Wi, bi, Wr, Wo, bo, tau, ta, 1.0f / (float)nx);
    k_main<<<B / TPB, TPB>>>(x, steps, out, hout);
}

// round 10
// speedup vs baseline: 1.9359x; 1.9359x over previous
#include <cuda_runtime.h>
#include <cstdint>

#define HD   19      // hidden size
#define HJ   20      // padded hidden (rows are 80B, 16B-aligned)
#define DD   64      // input size
#define TPB  128
#define NPART 1024

__device__ float g_partials[NPART];

struct Tables {
    float WiT[DD * HJ];   // [k][j] = Wi[j][k]
    float WrT[HD * HJ];   // [k][j] = Wr[j][k]
    float WoT[HD * HJ];   // [k][j] = Wo[j][k]
    float bi[HJ];
    float bo[HJ];
    float bdt[HJ];        // dt / tau_dyn, pad = 0
};
__device__ Tables g_tab;
#define TAB_F ((int)(sizeof(Tables) / 4))

static __device__ __forceinline__ float tanha(float v) {
    float r; asm("tanh.approx.f32 %0,%1;" : "=f"(r) : "f"(v)); return r;
}

// ---------- kernel A: per-block partial sums of |x| ----------
__global__ void __launch_bounds__(256) k_a_red(const float4* __restrict__ x, int n4) {
    float s = 0.f;
    for (int i = blockIdx.x * blockDim.x + threadIdx.x; i < n4;
         i += gridDim.x * blockDim.x) {
        float4 v = x[i];
        s += fabsf(v.x) + fabsf(v.y) + fabsf(v.z) + fabsf(v.w);
    }
#pragma unroll
    for (int o = 16; o > 0; o >>= 1) s += __shfl_down_sync(0xffffffffu, s, o);
    __shared__ float ws[8];
    int w = threadIdx.x >> 5, l = threadIdx.x & 31;
    if (l == 0) ws[w] = s;
    __syncthreads();
    if (threadIdx.x == 0) {
        float t = 0.f;
#pragma unroll
        for (int i = 0; i < 8; i++) t += ws[i];
        g_partials[blockIdx.x] = t;
    }
}

// ---------- kernel B: finish reduction + build transposed tables ----------
__global__ void __launch_bounds__(256) k_prep(
    const float* __restrict__ Wi, const float* __restrict__ bi,
    const float* __restrict__ Wr, const float* __restrict__ Wo,
    const float* __restrict__ bo, const float* __restrict__ tau,
    const float* __restrict__ ta, float invN)
{
    __shared__ float red[256];
    __shared__ float urg_s;
    int t = threadIdx.x;

    float s = 0.f;
    for (int i = t; i < NPART; i += 256) s += g_partials[i];
    red[t] = s;
    __syncthreads();
#pragma unroll
    for (int o = 128; o > 0; o >>= 1) {
        if (t < o) red[t] += red[t + o];
        __syncthreads();
    }
    if (t == 0) urg_s = fmaxf(red[0] * invN, 0.01f);

    float* gt = (float*)&g_tab;
    for (int i = t; i < TAB_F; i += 256) gt[i] = 0.f;
    __syncthreads();
    float urg = urg_s;

    for (int i = t; i < DD * HD; i += 256) {
        int k = i / HD, j = i % HD;
        g_tab.WiT[k * HJ + j] = Wi[j * DD + k];
    }
    for (int i = t; i < HD * HD; i += 256) {
        int k = i / HD, j = i % HD;
        g_tab.WrT[k * HJ + j] = Wr[j * HD + k];
        g_tab.WoT[k * HJ + j] = Wo[j * HD + k];
    }
    if (t < HD) {
        g_tab.bi[t] = bi[t];
        g_tab.bo[t] = bo[t];
        float td = tau[t] * (1.0f - ta[t]) + ta[t] / urg;
        td = fminf(fmaxf(td, 0.01f), 10.0f);
        g_tab.bdt[t] = 0.01f / td;
    }
}

// accumulate a[0..18] += hk * row(w4), row as 5 float4 (20th lane is pad)
#define ACC_ROW(acc, w4, hk)                                        \
    do {                                                            \
        float4 _w0 = (w4)[0], _w1 = (w4)[1], _w2 = (w4)[2];         \
        float4 _w3 = (w4)[3], _w4v = (w4)[4];                       \
        acc[0]  = fmaf((hk), _w0.x, acc[0]);                        \
        acc[1]  = fmaf((hk), _w0.y, acc[1]);                        \
        acc[2]  = fmaf((hk), _w0.z, acc[2]);                        \
        acc[3]  = fmaf((hk), _w0.w, acc[3]);                        \
        acc[4]  = fmaf((hk), _w1.x, acc[4]);                        \
        acc[5]  = fmaf((hk), _w1.y, acc[5]);                        \
        acc[6]  = fmaf((hk), _w1.z, acc[6]);                        \
        acc[7]  = fmaf((hk), _w1.w, acc[7]);                        \
        acc[8]  = fmaf((hk), _w2.x, acc[8]);                        \
        acc[9]  = fmaf((hk), _w2.y, acc[9]);                        \
        acc[10] = fmaf((hk), _w2.z, acc[10]);                       \
        acc[11] = fmaf((hk), _w2.w, acc[11]);                       \
        acc[12] = fmaf((hk), _w3.x, acc[12]);                       \
        acc[13] = fmaf((hk), _w3.y, acc[13]);                       \
        acc[14] = fmaf((hk), _w3.z, acc[14]);                       \
        acc[15] = fmaf((hk), _w3.w, acc[15]);                       \
        acc[16] = fmaf((hk), _w4v.x, acc[16]);                      \
        acc[17] = fmaf((hk), _w4v.y, acc[17]);                      \
        acc[18] = fmaf((hk), _w4v.z, acc[18]);                      \
    } while (0)

// ---------- kernel C: fused, scalar FFMA + float4 weight loads ----------
__global__ void __launch_bounds__(TPB)
k_main(const float* __restrict__ x, const int* __restrict__ steps_p,
       float* __restrict__ out, float* __restrict__ hout)
{
    __shared__ __align__(16) float sWi[DD * HJ];   // 5120 B
    __shared__ __align__(16) float sWr[HD * HJ];   // 1520 B
    __shared__ __align__(16) float sWo[HD * HJ];   // 1520 B
    __shared__ float sBi[HJ], sBo[HJ], sBd[HJ];
    __shared__ float fst[TPB * HD];                // 9728 B staging

    const int tid = threadIdx.x;
    {
        const float* gt = (const float*)&g_tab;
        for (int i = tid; i < DD * HJ; i += TPB) sWi[i] = gt[i];
        const float* g1 = gt + DD * HJ;
        for (int i = tid; i < HD * HJ; i += TPB) sWr[i] = g1[i];
        const float* g2 = g1 + HD * HJ;
        for (int i = tid; i < HD * HJ; i += TPB) sWo[i] = g2[i];
        const float* g3 = g2 + HD * HJ;
        if (tid < HJ) {
            sBi[tid] = g3[tid];
            sBo[tid] = g3[HJ + tid];
            sBd[tid] = g3[2 * HJ + tid];
        }
    }
    __syncthreads();

    const size_t row = (size_t)blockIdx.x * TPB + tid;
    const float4* xr = (const float4*)(x + row * DD);

    // ---- phase 1: mapped = x @ Wi^T + bi ----
    float m[HD];
#pragma unroll
    for (int j = 0; j < HD; j++) m[j] = sBi[j];
#pragma unroll 4
    for (int q = 0; q < DD / 4; q++) {
        float4 v = xr[q];
        float vv[4] = {v.x, v.y, v.z, v.w};
#pragma unroll
        for (int e = 0; e < 4; e++) {
            const float4* w4 = (const float4*)&sWi[(q * 4 + e) * HJ];
            float xk = vv[e];
            ACC_ROW(m, w4, xk);
        }
    }

    // ---- phase 2: recurrence ----
    float h[HD];
#pragma unroll
    for (int j = 0; j < HD; j++) h[j] = 0.f;

    const int steps = *steps_p;
    for (int s = 0; s < steps; s++) {
        float a[HD];
#pragma unroll
        for (int j = 0; j < HD; j++) a[j] = m[j];
#pragma unroll
        for (int k = 0; k < HD; k++) {
            const float4* w4 = (const float4*)&sWr[k * HJ];
            float hk = h[k];
            ACC_ROW(a, w4, hk);
        }
#pragma unroll
        for (int j = 0; j < HD; j++)
            h[j] = fmaf(sBd[j], tanha(a[j]) - h[j], h[j]);
    }

    // ---- phase 3: out = h @ Wo^T + bo (reuse m) ----
#pragma unroll
    for (int j = 0; j < HD; j++) m[j] = sBo[j];
#pragma unroll
    for (int k = 0; k < HD; k++) {
        const float4* w4 = (const float4*)&sWo[k * HJ];
        float hk = h[k];
        ACC_ROW(m, w4, hk);
    }

    // ---- stage + coalesced stores ----
#pragma unroll
    for (int j = 0; j < HD; j++) fst[tid * HD + j] = m[j];
    __syncthreads();
    {
        float4* go = (float4*)(out + (size_t)blockIdx.x * (TPB * HD));
        const float4* f4 = (const float4*)fst;
        for (int i = tid; i < TPB * HD / 4; i += TPB) go[i] = f4[i];
    }
    if (hout) {
        __syncthreads();
#pragma unroll
        for (int j = 0; j < HD; j++) fst[tid * HD + j] = h[j];
        __syncthreads();
        float4* gh = (float4*)(hout + (size_t)blockIdx.x * (TPB * HD));
        const float4* f4 = (const float4*)fst;
        for (int i = tid; i < TPB * HD / 4; i += TPB) gh[i] = f4[i];
    }
}

extern "C" void kernel_launch(void* const* d_in, const int* in_sizes, int n_in,
                              void* d_out, int out_size) {
    const float* x   = (const float*)d_in[0];
    const float* Wi  = (const float*)d_in[1];
    const float* bi  = (const float*)d_in[2];
    const float* Wr  = (const float*)d_in[3];
    const float* Wo  = (const float*)d_in[4];
    const float* bo  = (const float*)d_in[5];
    const float* tau = (const float*)d_in[6];
    const float* ta  = (const float*)d_in[7];
    const int* steps = (const int*)d_in[8];

    const int nx = in_sizes[0];
    const int B  = nx / DD;

    float* out = (float*)d_out;
    long long bh = (long long)B * HD;
    float* hout = ((long long)out_size >= 2 * bh) ? (out + bh) : nullptr;

    k_a_red<<<NPART, 256>>>((const float4*)x, nx / 4);
    k_prep<<<1, 256>>>(Wi, bi, Wr, Wo, bo, tau, ta, 1.0f / (float)nx);
    k_main<<<B / TPB, TPB>>>(x, steps, out, hout);
}

// round 11
// speedup vs baseline: 3.0298x; 1.5651x over previous
#include <cuda_runtime.h>
#include <cstdint>

#define HD   19      // hidden size
#define HJ   20      // padded hidden stride
#define DD   64      // input size
#define TPB  128
#define RPT  2       // batch rows per thread
#define RPB  (TPB * RPT)
#define NPART 1024

__device__ float g_partials[NPART];

struct Tables {
    float WiT[DD * HJ];   // [k][j] = Wi[j][k]
    float WrT[HD * HJ];   // [k][j] = Wr[j][k]
    float WoT[HD * HJ];   // [k][j] = Wo[j][k]
    float bi[HJ];
    float bo[HJ];
    float bdt[HJ];        // dt / tau_dyn
};
__device__ Tables g_tab;
#define TAB_F ((int)(sizeof(Tables) / 4))

static __device__ __forceinline__ float tanha(float v) {
    float r; asm("tanh.approx.f32 %0,%1;" : "=f"(r) : "f"(v)); return r;
}
// guaranteed-scalar shared load (prevents LDS.128 re-vectorization)
static __device__ __forceinline__ float lds32(uint32_t a) {
    float r; asm("ld.shared.f32 %0,[%1];" : "=f"(r) : "r"(a)); return r;
}
static __device__ __forceinline__ uint32_t saddr(const void* p) {
    uint32_t a;
    asm("{.reg .u64 t; cvta.to.shared.u64 t,%1; cvt.u32.u64 %0,t;}"
        : "=r"(a) : "l"(p));
    return a;
}

// ---------- kernel A: per-block partial sums of |x| ----------
__global__ void __launch_bounds__(256) k_a_red(const float4* __restrict__ x, int n4) {
    float s = 0.f;
    for (int i = blockIdx.x * blockDim.x + threadIdx.x; i < n4;
         i += gridDim.x * blockDim.x) {
        float4 v = x[i];
        s += fabsf(v.x) + fabsf(v.y) + fabsf(v.z) + fabsf(v.w);
    }
#pragma unroll
    for (int o = 16; o > 0; o >>= 1) s += __shfl_down_sync(0xffffffffu, s, o);
    __shared__ float ws[8];
    int w = threadIdx.x >> 5, l = threadIdx.x & 31;
    if (l == 0) ws[w] = s;
    __syncthreads();
    if (threadIdx.x == 0) {
        float t = 0.f;
#pragma unroll
        for (int i = 0; i < 8; i++) t += ws[i];
        g_partials[blockIdx.x] = t;
    }
}

// ---------- kernel B: finish reduction + build transposed tables ----------
__global__ void __launch_bounds__(256) k_prep(
    const float* __restrict__ Wi, const float* __restrict__ bi,
    const float* __restrict__ Wr, const float* __restrict__ Wo,
    const float* __restrict__ bo, const float* __restrict__ tau,
    const float* __restrict__ ta, float invN)
{
    __shared__ float red[256];
    __shared__ float urg_s;
    int t = threadIdx.x;

    float s = 0.f;
    for (int i = t; i < NPART; i += 256) s += g_partials[i];
    red[t] = s;
    __syncthreads();
#pragma unroll
    for (int o = 128; o > 0; o >>= 1) {
        if (t < o) red[t] += red[t + o];
        __syncthreads();
    }
    if (t == 0) urg_s = fmaxf(red[0] * invN, 0.01f);

    float* gt = (float*)&g_tab;
    for (int i = t; i < TAB_F; i += 256) gt[i] = 0.f;
    __syncthreads();
    float urg = urg_s;

    for (int i = t; i < DD * HD; i += 256) {
        int k = i / HD, j = i % HD;
        g_tab.WiT[k * HJ + j] = Wi[j * DD + k];
    }
    for (int i = t; i < HD * HD; i += 256) {
        int k = i / HD, j = i % HD;
        g_tab.WrT[k * HJ + j] = Wr[j * HD + k];
        g_tab.WoT[k * HJ + j] = Wo[j * HD + k];
    }
    if (t < HD) {
        g_tab.bi[t] = bi[t];
        g_tab.bo[t] = bo[t];
        float td = tau[t] * (1.0f - ta[t]) + ta[t] / urg;
        td = fminf(fmaxf(td, 0.01f), 10.0f);
        g_tab.bdt[t] = 0.01f / td;
    }
}

// ---------- kernel C: scalar FFMA + scalar LDS broadcast, 2 rows/thread ----------
__global__ void __launch_bounds__(TPB, 2)
k_main(const float* __restrict__ x, const int* __restrict__ steps_p,
       float* __restrict__ out, float* __restrict__ hout)
{
    __shared__ float sWi[DD * HJ];
    __shared__ float sWr[HD * HJ];
    __shared__ float sWo[HD * HJ];
    __shared__ float sBi[HJ], sBo[HJ], sBd[HJ];
    __shared__ float fst[RPB * HD];     // 19456 B staging

    const int tid = threadIdx.x;
    {
        const float* gt = (const float*)&g_tab;
        for (int i = tid; i < DD * HJ; i += TPB) sWi[i] = gt[i];
        const float* g1 = gt + DD * HJ;
        for (int i = tid; i < HD * HJ; i += TPB) sWr[i] = g1[i];
        const float* g2 = g1 + HD * HJ;
        for (int i = tid; i < HD * HJ; i += TPB) sWo[i] = g2[i];
        const float* g3 = g2 + HD * HJ;
        if (tid < HJ) {
            sBi[tid] = g3[tid];
            sBo[tid] = g3[HJ + tid];
            sBd[tid] = g3[2 * HJ + tid];
        }
    }
    __syncthreads();

    const uint32_t aWi = saddr(sWi);
    const uint32_t aWr = saddr(sWr);
    const uint32_t aWo = saddr(sWo);

    const size_t row0 = (size_t)blockIdx.x * RPB + tid;
    const float4* xr0 = (const float4*)(x + row0 * DD);
    const float4* xr1 = (const float4*)(x + (row0 + TPB) * DD);

    // ---- phase 1: mapped = x @ Wi^T + bi ----
    float m0[HD], m1[HD];
#pragma unroll
    for (int j = 0; j < HD; j++) { m0[j] = sBi[j]; m1[j] = sBi[j]; }
#pragma unroll 4
    for (int q = 0; q < DD / 4; q++) {
        float4 v0 = xr0[q];
        float4 v1 = xr1[q];
        float a0v[4] = {v0.x, v0.y, v0.z, v0.w};
        float a1v[4] = {v1.x, v1.y, v1.z, v1.w};
#pragma unroll
        for (int e = 0; e < 4; e++) {
            uint32_t wb = aWi + (uint32_t)((q * 4 + e) * HJ) * 4u;
            float xk0 = a0v[e], xk1 = a1v[e];
#pragma unroll
            for (int j = 0; j < HD; j++) {
                float w = lds32(wb + 4u * j);
                m0[j] = fmaf(xk0, w, m0[j]);
                m1[j] = fmaf(xk1, w, m1[j]);
            }
        }
    }

    // ---- phase 2: recurrence ----
    float h0[HD], h1[HD];
#pragma unroll
    for (int j = 0; j < HD; j++) { h0[j] = 0.f; h1[j] = 0.f; }

    const int steps = *steps_p;
    for (int s = 0; s < steps; s++) {
        float a0[HD], a1[HD];
#pragma unroll
        for (int j = 0; j < HD; j++) { a0[j] = m0[j]; a1[j] = m1[j]; }
#pragma unroll
        for (int k = 0; k < HD; k++) {
            uint32_t wb = aWr + (uint32_t)(k * HJ) * 4u;
            float hk0 = h0[k], hk1 = h1[k];
#pragma unroll
            for (int j = 0; j < HD; j++) {
                float w = lds32(wb + 4u * j);
                a0[j] = fmaf(hk0, w, a0[j]);
                a1[j] = fmaf(hk1, w, a1[j]);
            }
        }
#pragma unroll
        for (int j = 0; j < HD; j++) {
            float b = sBd[j];
            h0[j] = fmaf(b, tanha(a0[j]) - h0[j], h0[j]);
            h1[j] = fmaf(b, tanha(a1[j]) - h1[j], h1[j]);
        }
    }

    // ---- phase 3: out = h @ Wo^T + bo (reuse m regs) ----
#pragma unroll
    for (int j = 0; j < HD; j++) { m0[j] = sBo[j]; m1[j] = sBo[j]; }
#pragma unroll
    for (int k = 0; k < HD; k++) {
        uint32_t wb = aWo + (uint32_t)(k * HJ) * 4u;
        float hk0 = h0[k], hk1 = h1[k];
#pragma unroll
        for (int j = 0; j < HD; j++) {
            float w = lds32(wb + 4u * j);
            m0[j] = fmaf(hk0, w, m0[j]);
            m1[j] = fmaf(hk1, w, m1[j]);
        }
    }

    // ---- stage + coalesced stores ----
    __syncthreads();
#pragma unroll
    for (int j = 0; j < HD; j++) {
        fst[tid * HD + j]         = m0[j];
        fst[(TPB + tid) * HD + j] = m1[j];
    }
    __syncthreads();
    {
        float4* go = (float4*)(out + (size_t)blockIdx.x * (RPB * HD));
        const float4* f4 = (const float4*)fst;
        for (int i = tid; i < RPB * HD / 4; i += TPB) go[i] = f4[i];
    }
    if (hout) {
        __syncthreads();
#pragma unroll
        for (int j = 0; j < HD; j++) {
            fst[tid * HD + j]         = h0[j];
            fst[(TPB + tid) * HD + j] = h1[j];
        }
        __syncthreads();
        float4* gh = (float4*)(hout + (size_t)blockIdx.x * (RPB * HD));
        const float4* f4 = (const float4*)fst;
        for (int i = tid; i < RPB * HD / 4; i += TPB) gh[i] = f4[i];
    }
}

extern "C" void kernel_launch(void* const* d_in, const int* in_sizes, int n_in,
                              void* d_out, int out_size) {
    const float* x   = (const float*)d_in[0];
    const float* Wi  = (const float*)d_in[1];
    const float* bi  = (const float*)d_in[2];
    const float* Wr  = (const float*)d_in[3];
    const float* Wo  = (const float*)d_in[4];
    const float* bo  = (const float*)d_in[5];
    const float* tau = (const float*)d_in[6];
    const float* ta  = (const float*)d_in[7];
    const int* steps = (const int*)d_in[8];

    const int nx = in_sizes[0];
    const int B  = nx / DD;

    float* out = (float*)d_out;
    long long bh = (long long)B * HD;
    float* hout = ((long long)out_size >= 2 * bh) ? (out + bh) : nullptr;

    k_a_red<<<NPART, 256>>>((const float4*)x, nx / 4);
    k_prep<<<1, 256>>>(Wi, bi, Wr, Wo, bo, tau, ta, 1.0f / (float)nx);
    k_main<<<B / RPB, TPB>>>(x, steps, out, hout);
}